// round 3
// baseline (speedup 1.0000x reference)
#include <cuda_runtime.h>
#include <cuda_bf16.h>
#include <cstdint>

#define T_STEPS 4096
#define ISZ 1024
#define HSZ 2048
#define OSZ 64
#define NBLK 148
#define RT 256

// ---------------- device scratch (no allocations allowed) -------------------
__device__ float g_xproj[(size_t)T_STEPS * 4 * HSZ];  // [t][gate*H + j]
__device__ float g_hbuf[2 * HSZ];                     // double-buffered h
__device__ unsigned g_ctr;

// ---------------- init: zero h buffers + barrier counter --------------------
__global__ void init_kernel() {
    int i = blockIdx.x * blockDim.x + threadIdx.x;
    if (i < 2 * HSZ) g_hbuf[i] = 0.f;
    if (i == 0) g_ctr = 0u;
}

// ---------------- x-projection GEMM -----------------------------------------
// C[t][g*H + j] = x_t . Wg[j] + Wg_b[j] + Ug_b[j]
#define BM 128
#define BN 64
#define BK 16

__global__ __launch_bounds__(256) void xproj_kernel(
    const float* __restrict__ A,
    const float* __restrict__ W0, const float* __restrict__ W1,
    const float* __restrict__ W2, const float* __restrict__ W3,
    const float* __restrict__ Wb0, const float* __restrict__ Wb1,
    const float* __restrict__ Wb2, const float* __restrict__ Wb3,
    const float* __restrict__ Ub0, const float* __restrict__ Ub1,
    const float* __restrict__ Ub2, const float* __restrict__ Ub3)
{
    __shared__ float As[BK][BM + 4];
    __shared__ float Bs[BK][BN + 4];
    const int bn = blockIdx.x;           // 0..127 : gate = bn>>5, 32 col-tiles/gate
    const int bm = blockIdx.y;           // 0..31
    const int gate = bn >> 5;
    const int j0 = (bn & 31) * BN;
    const float* W  = (gate == 0) ? W0  : (gate == 1) ? W1  : (gate == 2) ? W2  : W3;
    const float* Wb = (gate == 0) ? Wb0 : (gate == 1) ? Wb1 : (gate == 2) ? Wb2 : Wb3;
    const float* Ub = (gate == 0) ? Ub0 : (gate == 1) ? Ub1 : (gate == 2) ? Ub2 : Ub3;
    const int m0 = bm * BM;
    const int tid = threadIdx.x;
    const int tm = tid >> 4, tn = tid & 15;

    float acc[8][4];
#pragma unroll
    for (int i = 0; i < 8; i++)
#pragma unroll
        for (int j = 0; j < 4; j++) acc[i][j] = 0.f;

    for (int k0 = 0; k0 < ISZ; k0 += BK) {
#pragma unroll
        for (int it = 0; it < 2; it++) {
            int e = tid + it * 256;
            int row = e >> 2, kq = e & 3;
            float4 v = *(const float4*)(A + (size_t)(m0 + row) * ISZ + k0 + kq * 4);
            As[kq * 4 + 0][row] = v.x; As[kq * 4 + 1][row] = v.y;
            As[kq * 4 + 2][row] = v.z; As[kq * 4 + 3][row] = v.w;
        }
        {
            int row = tid >> 2, kq = tid & 3;
            float4 v = *(const float4*)(W + (size_t)(j0 + row) * ISZ + k0 + kq * 4);
            Bs[kq * 4 + 0][row] = v.x; Bs[kq * 4 + 1][row] = v.y;
            Bs[kq * 4 + 2][row] = v.z; Bs[kq * 4 + 3][row] = v.w;
        }
        __syncthreads();
#pragma unroll
        for (int k = 0; k < BK; k++) {
            float a[8], bb[4];
#pragma unroll
            for (int i = 0; i < 8; i++) a[i] = As[k][tm * 8 + i];
#pragma unroll
            for (int j = 0; j < 4; j++) bb[j] = Bs[k][tn * 4 + j];
#pragma unroll
            for (int i = 0; i < 8; i++)
#pragma unroll
                for (int j = 0; j < 4; j++)
                    acc[i][j] = fmaf(a[i], bb[j], acc[i][j]);
        }
        __syncthreads();
    }

    float bias[4];
#pragma unroll
    for (int j = 0; j < 4; j++) {
        int col = j0 + tn * 4 + j;
        bias[j] = Wb[col] + Ub[col];
    }
#pragma unroll
    for (int i = 0; i < 8; i++) {
        int row = m0 + tm * 8 + i;
        float4 v = make_float4(acc[i][0] + bias[0], acc[i][1] + bias[1],
                               acc[i][2] + bias[2], acc[i][3] + bias[3]);
        *(float4*)(g_xproj + (size_t)row * (4 * HSZ) + gate * HSZ + j0 + tn * 4) = v;
    }
}

// ---------------- persistent recurrence kernel ------------------------------
#define WS_BYTES (14 * 4 * HSZ * 2)          /* 229376: up to 56 bf16 rows */
#define GATEV_OFF WS_BYTES
#define CST_OFF (WS_BYTES + 256)
#define SMEM_BYTES (WS_BYTES + 256 + 64)     /* 229696 <= 232448 */

__device__ __forceinline__ float blo(unsigned v) { return __uint_as_float(v << 16); }
__device__ __forceinline__ float bhi(unsigned v) { return __uint_as_float(v & 0xFFFF0000u); }
__device__ __forceinline__ float sigm(float x) { return 1.f / (1.f + expf(-x)); }

__global__ __launch_bounds__(RT, 1) void recur_kernel(
    const float* __restrict__ Uf, const float* __restrict__ Ui,
    const float* __restrict__ Uc, const float* __restrict__ Uo)
{
    extern __shared__ char smem[];
    float* gatev  = (float*)(smem + GATEV_OFF);
    float* cstate = (float*)(smem + CST_OFF);

    const int b = blockIdx.x;
    const int tid = threadIdx.x;
    const int warp = tid >> 5, lane = tid & 31;
    // blocks 0..123 own 14 h-indices, 124..147 own 13 (sum = 2048)
    const int cnt  = (b < 124) ? 14 : 13;
    const int base = b * 13 + ((b < 124) ? b : 124);
    const int R = 4 * cnt;

    // stage this block's U rows into SMEM as bf16 (row r = g*cnt + k)
    {
        const float* Us[4] = {Uf, Ui, Uc, Uo};
        for (int e = tid; e < R * 512; e += RT) {
            int r = e >> 9;
            int c4 = e & 511;
            int g = r / cnt;
            int k = r - g * cnt;
            float4 v = *(const float4*)(Us[g] + (size_t)(base + k) * HSZ + c4 * 4);
            unsigned lo = ((unsigned)__bfloat16_as_ushort(__float2bfloat16_rn(v.y)) << 16)
                        |  (unsigned)__bfloat16_as_ushort(__float2bfloat16_rn(v.x));
            unsigned hi = ((unsigned)__bfloat16_as_ushort(__float2bfloat16_rn(v.w)) << 16)
                        |  (unsigned)__bfloat16_as_ushort(__float2bfloat16_rn(v.z));
            *((uint2*)(smem + (size_t)r * 4096) + c4) = make_uint2(lo, hi);
        }
        if (tid < cnt) cstate[tid] = 0.f;
    }
    __syncthreads();

    for (int t = 0; t < T_STEPS; t++) {
        // prefetch this step's x-projections (owner threads only)
        float xf = 0.f, xi = 0.f, xc = 0.f, xo = 0.f;
        if (tid < cnt) {
            const float* xr = g_xproj + (size_t)t * (4 * HSZ);
            int j = base + tid;
            xf = __ldg(xr + j);
            xi = __ldg(xr + HSZ + j);
            xc = __ldg(xr + 2 * HSZ + j);
            xo = __ldg(xr + 3 * HSZ + j);
        }

        // lane owns h[4*lane + 128*i + j]  (L2 loads: h written by other SMs)
        const float4* hp = (const float4*)(g_hbuf + (t & 1) * HSZ) + lane;
        float hv[64];
#pragma unroll
        for (int i = 0; i < 16; i++) {
            float4 v = __ldcg(hp + i * 32);
            hv[i * 4 + 0] = v.x; hv[i * 4 + 1] = v.y;
            hv[i * 4 + 2] = v.z; hv[i * 4 + 3] = v.w;
        }

        // GEMV: warp w handles rows w, w+8, ...
        for (int r = warp; r < R; r += 8) {
            const uint2* wp = (const uint2*)(smem + (size_t)r * 4096) + lane;
            float a0 = 0.f, a1 = 0.f, a2 = 0.f, a3 = 0.f;
#pragma unroll
            for (int i = 0; i < 16; i++) {
                uint2 w = wp[i * 32];
                a0 = fmaf(blo(w.x), hv[i * 4 + 0], a0);
                a1 = fmaf(bhi(w.x), hv[i * 4 + 1], a1);
                a2 = fmaf(blo(w.y), hv[i * 4 + 2], a2);
                a3 = fmaf(bhi(w.y), hv[i * 4 + 3], a3);
            }
            float s = (a0 + a1) + (a2 + a3);
            s += __shfl_down_sync(0xffffffffu, s, 16);
            s += __shfl_down_sync(0xffffffffu, s, 8);
            s += __shfl_down_sync(0xffffffffu, s, 4);
            s += __shfl_down_sync(0xffffffffu, s, 2);
            s += __shfl_down_sync(0xffffffffu, s, 1);
            if (lane == 0) gatev[r] = s;
        }
        __syncthreads();

        // LSTM cell for this block's h-indices; write h_{t+1}
        if (tid < cnt) {
            float f  = sigm(gatev[tid]           + xf);
            float ig = sigm(gatev[cnt + tid]     + xi);
            float ch = tanhf(gatev[2 * cnt + tid] + xc);
            float o  = sigm(gatev[3 * cnt + tid] + xo);   // uses previous h (as ref)
            float c  = f * cstate[tid] + ig * ch;
            cstate[tid] = c;
            g_hbuf[((t + 1) & 1) * HSZ + base + tid] = o * tanhf(c);
            __threadfence();
        }
        __syncthreads();

        // grid barrier (release by writers above; acquire below)
        if (tid == 0) {
            atomicAdd(&g_ctr, 1u);
            unsigned target = (unsigned)(t + 1) * NBLK;
            while (*(volatile unsigned*)&g_ctr < target) { }
            __threadfence();
        }
        __syncthreads();
    }
}

// ---------------- head: fc + log_softmax (h_T lives in g_hbuf[0..H)) --------
__global__ void head_kernel(const float* __restrict__ fcw,
                            const float* __restrict__ fcb,
                            float* __restrict__ out)
{
    int lane = threadIdx.x;  // 32 threads, 2 outputs each
    const float* h = g_hbuf; // T_STEPS even -> final h in buffer 0
    float z0 = fcb[2 * lane], z1 = fcb[2 * lane + 1];
    const float* w0 = fcw + (size_t)(2 * lane) * HSZ;
    const float* w1 = fcw + (size_t)(2 * lane + 1) * HSZ;
    for (int k = 0; k < HSZ; k++) {
        float hv = h[k];
        z0 = fmaf(w0[k], hv, z0);
        z1 = fmaf(w1[k], hv, z1);
    }
    float m = fmaxf(z0, z1);
#pragma unroll
    for (int o = 16; o > 0; o >>= 1) m = fmaxf(m, __shfl_xor_sync(0xffffffffu, m, o));
    float s = expf(z0 - m) + expf(z1 - m);
#pragma unroll
    for (int o = 16; o > 0; o >>= 1) s += __shfl_xor_sync(0xffffffffu, s, o);
    float lse = m + logf(s);
    out[2 * lane]     = z0 - lse;
    out[2 * lane + 1] = z1 - lse;
}

// ---------------- launcher ---------------------------------------------------
extern "C" void kernel_launch(void* const* d_in, const int* in_sizes, int n_in,
                              void* d_out, int out_size)
{
    (void)in_sizes; (void)n_in; (void)out_size;
    const float* A    = (const float*)d_in[0];
    const float* Wf_w = (const float*)d_in[1];  const float* Wf_b = (const float*)d_in[2];
    const float* Uf_w = (const float*)d_in[3];  const float* Uf_b = (const float*)d_in[4];
    const float* Wi_w = (const float*)d_in[5];  const float* Wi_b = (const float*)d_in[6];
    const float* Ui_w = (const float*)d_in[7];  const float* Ui_b = (const float*)d_in[8];
    const float* Wc_w = (const float*)d_in[9];  const float* Wc_b = (const float*)d_in[10];
    const float* Uc_w = (const float*)d_in[11]; const float* Uc_b = (const float*)d_in[12];
    const float* Wo_w = (const float*)d_in[13]; const float* Wo_b = (const float*)d_in[14];
    const float* Uo_w = (const float*)d_in[15]; const float* Uo_b = (const float*)d_in[16];
    const float* fc_w = (const float*)d_in[17]; const float* fc_b = (const float*)d_in[18];
    float* out = (float*)d_out;

    cudaFuncSetAttribute(recur_kernel,
                         cudaFuncAttributeMaxDynamicSharedMemorySize, SMEM_BYTES);

    init_kernel<<<16, 256>>>();
    dim3 g(128, 32);
    xproj_kernel<<<g, 256>>>(A, Wf_w, Wi_w, Wc_w, Wo_w,
                             Wf_b, Wi_b, Wc_b, Wo_b,
                             Uf_b, Ui_b, Uc_b, Uo_b);
    recur_kernel<<<NBLK, RT, SMEM_BYTES>>>(Uf_w, Ui_w, Uc_w, Uo_w);
    head_kernel<<<1, 32>>>(fc_w, fc_b, out);
}

// round 4
// speedup vs baseline: 1.0148x; 1.0148x over previous
#include <cuda_runtime.h>
#include <cuda_bf16.h>
#include <cstdint>

#define T_STEPS 4096
#define ISZ 1024
#define HSZ 2048
#define OSZ 64
#define NBLK 148
#define RT 256

// ---------------- device scratch (no allocations allowed) -------------------
__device__ float g_xproj[(size_t)T_STEPS * 4 * HSZ];  // [t][gate*H + j]
__device__ float g_hbuf[2 * HSZ];                     // double-buffered h
__device__ unsigned g_ctr;

// ---------------- init: zero h buffers + barrier counter --------------------
__global__ void init_kernel() {
    int i = blockIdx.x * blockDim.x + threadIdx.x;
    if (i < 2 * HSZ) g_hbuf[i] = 0.f;
    if (i == 0) g_ctr = 0u;
}

// ---------------- x-projection GEMM -----------------------------------------
#define BM 128
#define BN 64
#define BK 16

__global__ __launch_bounds__(256) void xproj_kernel(
    const float* __restrict__ A,
    const float* __restrict__ W0, const float* __restrict__ W1,
    const float* __restrict__ W2, const float* __restrict__ W3,
    const float* __restrict__ Wb0, const float* __restrict__ Wb1,
    const float* __restrict__ Wb2, const float* __restrict__ Wb3,
    const float* __restrict__ Ub0, const float* __restrict__ Ub1,
    const float* __restrict__ Ub2, const float* __restrict__ Ub3)
{
    __shared__ float As[BK][BM + 4];
    __shared__ float Bs[BK][BN + 4];
    const int bn = blockIdx.x;
    const int bm = blockIdx.y;
    const int gate = bn >> 5;
    const int j0 = (bn & 31) * BN;
    const float* W  = (gate == 0) ? W0  : (gate == 1) ? W1  : (gate == 2) ? W2  : W3;
    const float* Wb = (gate == 0) ? Wb0 : (gate == 1) ? Wb1 : (gate == 2) ? Wb2 : Wb3;
    const float* Ub = (gate == 0) ? Ub0 : (gate == 1) ? Ub1 : (gate == 2) ? Ub2 : Ub3;
    const int m0 = bm * BM;
    const int tid = threadIdx.x;
    const int tm = tid >> 4, tn = tid & 15;

    float acc[8][4];
#pragma unroll
    for (int i = 0; i < 8; i++)
#pragma unroll
        for (int j = 0; j < 4; j++) acc[i][j] = 0.f;

    for (int k0 = 0; k0 < ISZ; k0 += BK) {
#pragma unroll
        for (int it = 0; it < 2; it++) {
            int e = tid + it * 256;
            int row = e >> 2, kq = e & 3;
            float4 v = *(const float4*)(A + (size_t)(m0 + row) * ISZ + k0 + kq * 4);
            As[kq * 4 + 0][row] = v.x; As[kq * 4 + 1][row] = v.y;
            As[kq * 4 + 2][row] = v.z; As[kq * 4 + 3][row] = v.w;
        }
        {
            int row = tid >> 2, kq = tid & 3;
            float4 v = *(const float4*)(W + (size_t)(j0 + row) * ISZ + k0 + kq * 4);
            Bs[kq * 4 + 0][row] = v.x; Bs[kq * 4 + 1][row] = v.y;
            Bs[kq * 4 + 2][row] = v.z; Bs[kq * 4 + 3][row] = v.w;
        }
        __syncthreads();
#pragma unroll
        for (int k = 0; k < BK; k++) {
            float a[8], bb[4];
#pragma unroll
            for (int i = 0; i < 8; i++) a[i] = As[k][tm * 8 + i];
#pragma unroll
            for (int j = 0; j < 4; j++) bb[j] = Bs[k][tn * 4 + j];
#pragma unroll
            for (int i = 0; i < 8; i++)
#pragma unroll
                for (int j = 0; j < 4; j++)
                    acc[i][j] = fmaf(a[i], bb[j], acc[i][j]);
        }
        __syncthreads();
    }

    float bias[4];
#pragma unroll
    for (int j = 0; j < 4; j++) {
        int col = j0 + tn * 4 + j;
        bias[j] = Wb[col] + Ub[col];
    }
#pragma unroll
    for (int i = 0; i < 8; i++) {
        int row = m0 + tm * 8 + i;
        float4 v = make_float4(acc[i][0] + bias[0], acc[i][1] + bias[1],
                               acc[i][2] + bias[2], acc[i][3] + bias[3]);
        *(float4*)(g_xproj + (size_t)row * (4 * HSZ) + gate * HSZ + j0 + tn * 4) = v;
    }
}

// ---------------- persistent recurrence kernel ------------------------------
#define WS_BYTES (14 * 4 * HSZ * 2)          /* 229376: up to 56 bf16 rows */
#define SMEM_BYTES (WS_BYTES + 512)          /* + gatev[2][64] */

__device__ __forceinline__ float sigm(float x) { return 1.f / (1.f + __expf(-x)); }
__device__ __forceinline__ float tanh_fast(float x) {
    return 1.f - __fdividef(2.f, __expf(2.f * x) + 1.f);
}

// acc.{lo,hi} += {bf16lo(w), bf16hi(w)} * h2.{lo,hi}   (packed fp32 FMA)
__device__ __forceinline__ void bffma2(unsigned long long& acc, unsigned w,
                                       unsigned long long h2) {
    asm("{\n\t"
        ".reg .b32 lo, hi;\n\t"
        ".reg .b64 wf;\n\t"
        "shl.b32 lo, %1, 16;\n\t"
        "and.b32 hi, %1, 0xFFFF0000;\n\t"
        "mov.b64 wf, {lo, hi};\n\t"
        "fma.rn.f32x2 %0, wf, %2, %0;\n\t"
        "}" : "+l"(acc) : "r"(w), "l"(h2));
}
__device__ __forceinline__ unsigned long long packf2(float a, float b) {
    unsigned long long r;
    asm("mov.b64 %0, {%1, %2};" : "=l"(r) : "f"(a), "f"(b));
    return r;
}
__device__ __forceinline__ float2 unpackf2(unsigned long long v) {
    float2 r;
    asm("mov.b64 {%0, %1}, %2;" : "=f"(r.x), "=f"(r.y) : "l"(v));
    return r;
}
__device__ __forceinline__ unsigned ldacq(const unsigned* p) {
    unsigned v;
    asm volatile("ld.acquire.gpu.global.u32 %0, [%1];" : "=r"(v) : "l"(p));
    return v;
}

__global__ __launch_bounds__(RT, 1) void recur_kernel(
    const float* __restrict__ Uf, const float* __restrict__ Ui,
    const float* __restrict__ Uc, const float* __restrict__ Uo)
{
    extern __shared__ char smem[];
    float* gatev = (float*)(smem + WS_BYTES);   // [2][64] half-partials

    const int b = blockIdx.x;
    const int tid = threadIdx.x;
    const int warp = tid >> 5, lane = tid & 31;
    const int cnt  = (b < 124) ? 14 : 13;       // h-indices owned (sum = 2048)
    const int base = b * 13 + ((b < 124) ? b : 124);
    const int R = 4 * cnt;                      // gate-rows in SMEM
    const int half = warp & 1;                  // this warp's h half

    // ---- stage U rows into SMEM as packed bf16 pairs (cols 2p, 2p+1) ----
    {
        const float* Us[4] = {Uf, Ui, Uc, Uo};
        for (int e = tid; e < R * 512; e += RT) {
            int r = e >> 9;
            int c4 = e & 511;
            int g = r / cnt;
            int k = r - g * cnt;
            float4 v = *(const float4*)(Us[g] + (size_t)(base + k) * HSZ + c4 * 4);
            unsigned lo = ((unsigned)__bfloat16_as_ushort(__float2bfloat16_rn(v.y)) << 16)
                        |  (unsigned)__bfloat16_as_ushort(__float2bfloat16_rn(v.x));
            unsigned hi = ((unsigned)__bfloat16_as_ushort(__float2bfloat16_rn(v.w)) << 16)
                        |  (unsigned)__bfloat16_as_ushort(__float2bfloat16_rn(v.z));
            *((uint2*)(smem + (size_t)r * 4096) + c4) = make_uint2(lo, hi);
        }
    }
    __syncthreads();

    float cst = 0.f;                            // cell state (warp0 lanes<cnt)
    float xf = 0.f, xi = 0.f, xc = 0.f, xo = 0.f;
    if (warp == 0 && lane < cnt) {
        const float* xr = g_xproj;
        int j = base + lane;
        xf = __ldg(xr + j);
        xi = __ldg(xr + HSZ + j);
        xc = __ldg(xr + 2 * HSZ + j);
        xo = __ldg(xr + 3 * HSZ + j);
    }

    // warp-local weight base: half offset (2048B = 256 uint2) + lane
    const uint2* wb = (const uint2*)smem + half * 256 + lane;

    for (int t = 0; t < T_STEPS; t++) {
        // ---- load this warp's h half: 32 floats/lane, packed into f32x2 ----
        const float4* hp = (const float4*)(g_hbuf + (t & 1) * HSZ + half * 1024) + lane;
        unsigned long long hvp[16];
#pragma unroll
        for (int i = 0; i < 8; i++) {
            float4 v = __ldcg(hp + i * 32);
            hvp[2 * i]     = packf2(v.x, v.y);
            hvp[2 * i + 1] = packf2(v.z, v.w);
        }

        // ---- GEMV half-rows: warp handles rows r = warp/2 + 4m, two at a time
        const int rbase = warp >> 1;
        int m = 0;
        for (; m + 1 < cnt; m += 2) {
            int r0 = rbase + 4 * m;
            int r1 = r0 + 4;
            const uint2* w0p = wb + r0 * 512;
            const uint2* w1p = wb + r1 * 512;
            unsigned long long accA = 0ull, accB = 0ull;
#pragma unroll
            for (int i = 0; i < 8; i++) {
                uint2 w0 = w0p[i * 32];
                uint2 w1 = w1p[i * 32];
                bffma2(accA, w0.x, hvp[2 * i]);
                bffma2(accA, w0.y, hvp[2 * i + 1]);
                bffma2(accB, w1.x, hvp[2 * i]);
                bffma2(accB, w1.y, hvp[2 * i + 1]);
            }
            float2 a = unpackf2(accA), c2 = unpackf2(accB);
            float sA = a.x + a.y, sB = c2.x + c2.y;
#pragma unroll
            for (int o = 16; o > 0; o >>= 1) {
                sA += __shfl_down_sync(0xffffffffu, sA, o);
                sB += __shfl_down_sync(0xffffffffu, sB, o);
            }
            if (lane == 0) {
                gatev[half * 64 + r0] = sA;
                gatev[half * 64 + r1] = sB;
            }
        }
        if (m < cnt) {                           // odd tail (cnt = 13)
            int r0 = rbase + 4 * m;
            const uint2* w0p = wb + r0 * 512;
            unsigned long long accA = 0ull;
#pragma unroll
            for (int i = 0; i < 8; i++) {
                uint2 w0 = w0p[i * 32];
                bffma2(accA, w0.x, hvp[2 * i]);
                bffma2(accA, w0.y, hvp[2 * i + 1]);
            }
            float2 a = unpackf2(accA);
            float sA = a.x + a.y;
#pragma unroll
            for (int o = 16; o > 0; o >>= 1)
                sA += __shfl_down_sync(0xffffffffu, sA, o);
            if (lane == 0) gatev[half * 64 + r0] = sA;
        }
        __syncthreads();                         // gatev partials complete

        // ---- cell update (warp 0), publish h_{t+1}, arrive ----
        if (warp == 0) {
            if (lane < cnt) {
                float f  = sigm(gatev[lane]               + gatev[64 + lane]               + xf);
                float ig = sigm(gatev[cnt + lane]         + gatev[64 + cnt + lane]         + xi);
                float ch = tanh_fast(gatev[2 * cnt + lane] + gatev[64 + 2 * cnt + lane]    + xc);
                float o  = sigm(gatev[3 * cnt + lane]     + gatev[64 + 3 * cnt + lane]     + xo);
                float c  = f * cst + ig * ch;
                cst = c;
                __stcg(&g_hbuf[((t + 1) & 1) * HSZ + base + lane], o * tanh_fast(c));
            }
            __syncwarp();
            if (lane == 0) { __threadfence(); atomicAdd(&g_ctr, 1u); }
            if (lane < cnt && t + 1 < T_STEPS) { // prefetch next x before spin
                const float* xr = g_xproj + (size_t)(t + 1) * (4 * HSZ);
                int j = base + lane;
                xf = __ldg(xr + j);
                xi = __ldg(xr + HSZ + j);
                xc = __ldg(xr + 2 * HSZ + j);
                xo = __ldg(xr + 3 * HSZ + j);
            }
        }

        // ---- grid barrier: spin with acquire load ----
        unsigned target = (unsigned)(t + 1) * NBLK;
        while (ldacq(&g_ctr) < target) { }
        // no syncthreads needed: no thread passes until this block arrived,
        // and this block arrives only after warp0 consumed gatev.
    }
}

// ---------------- head: fc + log_softmax, 1024 threads ----------------------
__global__ __launch_bounds__(1024) void head_kernel(
    const float* __restrict__ fcw, const float* __restrict__ fcb,
    float* __restrict__ out)
{
    __shared__ float zs[OSZ];
    const int tid = threadIdx.x;
    const int warp = tid >> 5, lane = tid & 31;     // 32 warps, 2 outputs each
    const float* h = g_hbuf;                        // final h (buffer 0)
    const int o0 = 2 * warp, o1 = o0 + 1;
    const float* w0 = fcw + (size_t)o0 * HSZ;
    const float* w1 = fcw + (size_t)o1 * HSZ;
    float z0 = 0.f, z1 = 0.f;
#pragma unroll
    for (int i = 0; i < 16; i++) {
        int c = i * 128 + lane * 4;
        float4 hv = *(const float4*)(h + c);
        float4 a  = *(const float4*)(w0 + c);
        float4 bq = *(const float4*)(w1 + c);
        z0 = fmaf(a.x, hv.x, fmaf(a.y, hv.y, fmaf(a.z, hv.z, fmaf(a.w, hv.w, z0))));
        z1 = fmaf(bq.x, hv.x, fmaf(bq.y, hv.y, fmaf(bq.z, hv.z, fmaf(bq.w, hv.w, z1))));
    }
#pragma unroll
    for (int o = 16; o > 0; o >>= 1) {
        z0 += __shfl_down_sync(0xffffffffu, z0, o);
        z1 += __shfl_down_sync(0xffffffffu, z1, o);
    }
    if (lane == 0) { zs[o0] = z0 + fcb[o0]; zs[o1] = z1 + fcb[o1]; }
    __syncthreads();
    if (warp == 0) {
        float a = zs[2 * lane], bq = zs[2 * lane + 1];
        float mx = fmaxf(a, bq);
#pragma unroll
        for (int o = 16; o > 0; o >>= 1) mx = fmaxf(mx, __shfl_xor_sync(0xffffffffu, mx, o));
        float s = expf(a - mx) + expf(bq - mx);
#pragma unroll
        for (int o = 16; o > 0; o >>= 1) s += __shfl_xor_sync(0xffffffffu, s, o);
        float lse = mx + logf(s);
        out[2 * lane]     = a - lse;
        out[2 * lane + 1] = bq - lse;
    }
}

// ---------------- launcher ---------------------------------------------------
extern "C" void kernel_launch(void* const* d_in, const int* in_sizes, int n_in,
                              void* d_out, int out_size)
{
    (void)in_sizes; (void)n_in; (void)out_size;
    const float* A    = (const float*)d_in[0];
    const float* Wf_w = (const float*)d_in[1];  const float* Wf_b = (const float*)d_in[2];
    const float* Uf_w = (const float*)d_in[3];  const float* Uf_b = (const float*)d_in[4];
    const float* Wi_w = (const float*)d_in[5];  const float* Wi_b = (const float*)d_in[6];
    const float* Ui_w = (const float*)d_in[7];  const float* Ui_b = (const float*)d_in[8];
    const float* Wc_w = (const float*)d_in[9];  const float* Wc_b = (const float*)d_in[10];
    const float* Uc_w = (const float*)d_in[11]; const float* Uc_b = (const float*)d_in[12];
    const float* Wo_w = (const float*)d_in[13]; const float* Wo_b = (const float*)d_in[14];
    const float* Uo_w = (const float*)d_in[15]; const float* Uo_b = (const float*)d_in[16];
    const float* fc_w = (const float*)d_in[17]; const float* fc_b = (const float*)d_in[18];
    float* out = (float*)d_out;

    cudaFuncSetAttribute(recur_kernel,
                         cudaFuncAttributeMaxDynamicSharedMemorySize, SMEM_BYTES);

    init_kernel<<<16, 256>>>();
    dim3 g(128, 32);
    xproj_kernel<<<g, 256>>>(A, Wf_w, Wi_w, Wc_w, Wo_w,
                             Wf_b, Wi_b, Wc_b, Wo_b,
                             Uf_b, Ui_b, Uc_b, Uo_b);
    recur_kernel<<<NBLK, RT, SMEM_BYTES>>>(Uf_w, Ui_w, Uc_w, Uo_w);
    head_kernel<<<1, 1024>>>(fc_w, fc_b, out);
}

// round 5
// speedup vs baseline: 1.1037x; 1.0875x over previous
#include <cuda_runtime.h>
#include <cuda_bf16.h>
#include <cstdint>

#define T_STEPS 4096
#define ISZ 1024
#define HSZ 2048
#define OSZ 64
#define NBLK 148
#define RT 256

// ---------------- device scratch (no allocations allowed) -------------------
__device__ float g_xproj[(size_t)T_STEPS * 4 * HSZ];  // [t][gate*H + j]
__device__ unsigned short g_hb[2 * HSZ];              // double-buffered h (bf16)
__device__ unsigned g_ctr, g_go;

// ---------------- init: zero h buffers + barrier state ----------------------
__global__ void init_kernel() {
    int i = blockIdx.x * blockDim.x + threadIdx.x;
    if (i < 2 * HSZ) g_hb[i] = 0;
    if (i == 0) { g_ctr = 0u; g_go = 0u; }
}

// ---------------- x-projection GEMM (unchanged, measured ~2.6ms) ------------
#define BM 128
#define BN 64
#define BK 16

__global__ __launch_bounds__(256) void xproj_kernel(
    const float* __restrict__ A,
    const float* __restrict__ W0, const float* __restrict__ W1,
    const float* __restrict__ W2, const float* __restrict__ W3,
    const float* __restrict__ Wb0, const float* __restrict__ Wb1,
    const float* __restrict__ Wb2, const float* __restrict__ Wb3,
    const float* __restrict__ Ub0, const float* __restrict__ Ub1,
    const float* __restrict__ Ub2, const float* __restrict__ Ub3)
{
    __shared__ float As[BK][BM + 4];
    __shared__ float Bs[BK][BN + 4];
    const int bn = blockIdx.x;
    const int bm = blockIdx.y;
    const int gate = bn >> 5;
    const int j0 = (bn & 31) * BN;
    const float* W  = (gate == 0) ? W0  : (gate == 1) ? W1  : (gate == 2) ? W2  : W3;
    const float* Wb = (gate == 0) ? Wb0 : (gate == 1) ? Wb1 : (gate == 2) ? Wb2 : Wb3;
    const float* Ub = (gate == 0) ? Ub0 : (gate == 1) ? Ub1 : (gate == 2) ? Ub2 : Ub3;
    const int m0 = bm * BM;
    const int tid = threadIdx.x;
    const int tm = tid >> 4, tn = tid & 15;

    float acc[8][4];
#pragma unroll
    for (int i = 0; i < 8; i++)
#pragma unroll
        for (int j = 0; j < 4; j++) acc[i][j] = 0.f;

    for (int k0 = 0; k0 < ISZ; k0 += BK) {
#pragma unroll
        for (int it = 0; it < 2; it++) {
            int e = tid + it * 256;
            int row = e >> 2, kq = e & 3;
            float4 v = *(const float4*)(A + (size_t)(m0 + row) * ISZ + k0 + kq * 4);
            As[kq * 4 + 0][row] = v.x; As[kq * 4 + 1][row] = v.y;
            As[kq * 4 + 2][row] = v.z; As[kq * 4 + 3][row] = v.w;
        }
        {
            int row = tid >> 2, kq = tid & 3;
            float4 v = *(const float4*)(W + (size_t)(j0 + row) * ISZ + k0 + kq * 4);
            Bs[kq * 4 + 0][row] = v.x; Bs[kq * 4 + 1][row] = v.y;
            Bs[kq * 4 + 2][row] = v.z; Bs[kq * 4 + 3][row] = v.w;
        }
        __syncthreads();
#pragma unroll
        for (int k = 0; k < BK; k++) {
            float a[8], bb[4];
#pragma unroll
            for (int i = 0; i < 8; i++) a[i] = As[k][tm * 8 + i];
#pragma unroll
            for (int j = 0; j < 4; j++) bb[j] = Bs[k][tn * 4 + j];
#pragma unroll
            for (int i = 0; i < 8; i++)
#pragma unroll
                for (int j = 0; j < 4; j++)
                    acc[i][j] = fmaf(a[i], bb[j], acc[i][j]);
        }
        __syncthreads();
    }

    float bias[4];
#pragma unroll
    for (int j = 0; j < 4; j++) {
        int col = j0 + tn * 4 + j;
        bias[j] = Wb[col] + Ub[col];
    }
#pragma unroll
    for (int i = 0; i < 8; i++) {
        int row = m0 + tm * 8 + i;
        float4 v = make_float4(acc[i][0] + bias[0], acc[i][1] + bias[1],
                               acc[i][2] + bias[2], acc[i][3] + bias[3]);
        *(float4*)(g_xproj + (size_t)row * (4 * HSZ) + gate * HSZ + j0 + tn * 4) = v;
    }
}

// ---------------- persistent recurrence kernel ------------------------------
#define WS_BYTES (14 * 4 * HSZ * 2)          /* 229376: up to 56 bf16 rows */
#define SMEM_BYTES (WS_BYTES + 512)          /* + gatev[2][64] */

__device__ __forceinline__ float sigm(float x) { return 1.f / (1.f + __expf(-x)); }
__device__ __forceinline__ float tanh_fast(float x) {
    return 1.f - __fdividef(2.f, __expf(2.f * x) + 1.f);
}

// acc.{lo,hi} += {bf16lo(w), bf16hi(w)} * h2.{lo,hi}   (packed fp32 FMA)
__device__ __forceinline__ void bffma2(unsigned long long& acc, unsigned w,
                                       unsigned long long h2) {
    asm("{\n\t"
        ".reg .b32 lo, hi;\n\t"
        ".reg .b64 wf;\n\t"
        "shl.b32 lo, %1, 16;\n\t"
        "and.b32 hi, %1, 0xFFFF0000;\n\t"
        "mov.b64 wf, {lo, hi};\n\t"
        "fma.rn.f32x2 %0, wf, %2, %0;\n\t"
        "}" : "+l"(acc) : "r"(w), "l"(h2));
}
// bf16 pair (packed in u32) -> f32x2 register pair
__device__ __forceinline__ unsigned long long bf2f2(unsigned u) {
    unsigned long long r;
    asm("{\n\t"
        ".reg .b32 lo, hi;\n\t"
        "shl.b32 lo, %1, 16;\n\t"
        "and.b32 hi, %1, 0xFFFF0000;\n\t"
        "mov.b64 %0, {lo, hi};\n\t"
        "}" : "=l"(r) : "r"(u));
    return r;
}
__device__ __forceinline__ float2 unpackf2(unsigned long long v) {
    float2 r;
    asm("mov.b64 {%0, %1}, %2;" : "=f"(r.x), "=f"(r.y) : "l"(v));
    return r;
}
__device__ __forceinline__ unsigned ldacq(const unsigned* p) {
    unsigned v;
    asm volatile("ld.acquire.gpu.u32 %0, [%1];" : "=r"(v) : "l"(p));
    return v;
}
__device__ __forceinline__ unsigned atomrel_add(unsigned* p) {
    unsigned old;
    asm volatile("atom.release.gpu.add.u32 %0, [%1], 1;" : "=r"(old) : "l"(p));
    return old;
}
__device__ __forceinline__ void strel(unsigned* p, unsigned v) {
    asm volatile("st.release.gpu.u32 [%0], %1;" :: "l"(p), "r"(v));
}
__device__ __forceinline__ void st16cg(unsigned short* p, unsigned short v) {
    asm volatile("st.global.cg.u16 [%0], %1;" :: "l"(p), "h"(v));
}

template<int CNT>
__device__ __forceinline__ void run_steps(char* smem, float* gatev,
                                          int base, int warp, int lane)
{
    const int half = warp & 1;
    const int rbase = warp >> 1;
    // this warp's weight view: row r half -> bytes r*4096 + half*2048 + lane*16
    const uint4* wb = (const uint4*)(smem + half * 2048) + lane;

    float cst = 0.f;
    float xf = 0.f, xi = 0.f, xc = 0.f, xo = 0.f;
    if (warp == 0 && lane < CNT) {
        const float* xr = g_xproj;
        int j = base + lane;
        xf = __ldg(xr + j);
        xi = __ldg(xr + HSZ + j);
        xc = __ldg(xr + 2 * HSZ + j);
        xo = __ldg(xr + 3 * HSZ + j);
    }

    for (int t = 0; t < T_STEPS; t++) {
        // ---- load this warp's h half (bf16) and unpack to f32x2 ----
        const uint4* hp = (const uint4*)(g_hb + (t & 1) * HSZ + half * 1024) + lane;
        unsigned long long hv[16];
#pragma unroll
        for (int i = 0; i < 4; i++) {
            uint4 v = __ldcg(hp + i * 32);
            hv[4 * i + 0] = bf2f2(v.x);
            hv[4 * i + 1] = bf2f2(v.y);
            hv[4 * i + 2] = bf2f2(v.z);
            hv[4 * i + 3] = bf2f2(v.w);
        }

        // ---- GEMV half-rows, fully unrolled, two rows per iteration ----
#pragma unroll
        for (int m = 0; m + 1 < CNT; m += 2) {
            const int r0 = 4 * m + rbase;
            const int r1 = r0 + 4;
            const uint4* wA = wb + r0 * 256;
            const uint4* wB = wb + r1 * 256;
            unsigned long long accA = 0ull, accB = 0ull;
#pragma unroll
            for (int i = 0; i < 4; i++) {
                uint4 a = wA[i * 32];
                uint4 b = wB[i * 32];
                bffma2(accA, a.x, hv[4 * i + 0]);
                bffma2(accA, a.y, hv[4 * i + 1]);
                bffma2(accA, a.z, hv[4 * i + 2]);
                bffma2(accA, a.w, hv[4 * i + 3]);
                bffma2(accB, b.x, hv[4 * i + 0]);
                bffma2(accB, b.y, hv[4 * i + 1]);
                bffma2(accB, b.z, hv[4 * i + 2]);
                bffma2(accB, b.w, hv[4 * i + 3]);
            }
            float2 a2 = unpackf2(accA), b2 = unpackf2(accB);
            float sA = a2.x + a2.y, sB = b2.x + b2.y;
#pragma unroll
            for (int o = 16; o > 0; o >>= 1) {
                sA += __shfl_down_sync(0xffffffffu, sA, o);
                sB += __shfl_down_sync(0xffffffffu, sB, o);
            }
            if (lane == 0) {
                gatev[half * 64 + r0] = sA;
                gatev[half * 64 + r1] = sB;
            }
        }
        if (CNT & 1) {                           // odd tail (CNT = 13)
            const int r0 = 4 * (CNT - 1) + rbase;
            const uint4* wA = wb + r0 * 256;
            unsigned long long accA = 0ull;
#pragma unroll
            for (int i = 0; i < 4; i++) {
                uint4 a = wA[i * 32];
                bffma2(accA, a.x, hv[4 * i + 0]);
                bffma2(accA, a.y, hv[4 * i + 1]);
                bffma2(accA, a.z, hv[4 * i + 2]);
                bffma2(accA, a.w, hv[4 * i + 3]);
            }
            float2 a2 = unpackf2(accA);
            float sA = a2.x + a2.y;
#pragma unroll
            for (int o = 16; o > 0; o >>= 1)
                sA += __shfl_down_sync(0xffffffffu, sA, o);
            if (lane == 0) gatev[half * 64 + r0] = sA;
        }
        __syncthreads();                         // (A) gatev complete

        // ---- warp 0: cell update, publish h_{t+1}, arrive, spin ----
        if (warp == 0) {
            if (lane < CNT) {
                float f  = sigm(gatev[lane]                + gatev[64 + lane]                + xf);
                float ig = sigm(gatev[CNT + lane]          + gatev[64 + CNT + lane]          + xi);
                float ch = tanh_fast(gatev[2 * CNT + lane] + gatev[64 + 2 * CNT + lane]      + xc);
                float o  = sigm(gatev[3 * CNT + lane]      + gatev[64 + 3 * CNT + lane]      + xo);
                float c  = f * cst + ig * ch;
                cst = c;
                unsigned short hb = __bfloat16_as_ushort(__float2bfloat16_rn(o * tanh_fast(c)));
                st16cg(&g_hb[((t + 1) & 1) * HSZ + base + lane], hb);
            }
            __syncwarp();
            unsigned old = 0;
            if (lane == 0) {
                __threadfence();
                old = atomrel_add(&g_ctr);
                if (old == (unsigned)t * NBLK + (NBLK - 1))
                    strel(&g_go, (unsigned)(t + 1));
            }
            if (lane < CNT && t + 1 < T_STEPS) { // prefetch next x (off path)
                const float* xr = g_xproj + (size_t)(t + 1) * (4 * HSZ);
                int j = base + lane;
                xf = __ldg(xr + j);
                xi = __ldg(xr + HSZ + j);
                xc = __ldg(xr + 2 * HSZ + j);
                xo = __ldg(xr + 3 * HSZ + j);
            }
            if (lane == 0) {                     // sole spinner per block
                while (ldacq(&g_go) < (unsigned)(t + 1)) { }
            }
        }
        __syncthreads();                         // (B) h_{t+1} visible
    }
}

__global__ __launch_bounds__(RT, 1) void recur_kernel(
    const float* __restrict__ Uf, const float* __restrict__ Ui,
    const float* __restrict__ Uc, const float* __restrict__ Uo)
{
    extern __shared__ char smem[];
    float* gatev = (float*)(smem + WS_BYTES);   // [2][64] half-partials

    const int b = blockIdx.x;
    const int tid = threadIdx.x;
    const int warp = tid >> 5, lane = tid & 31;
    const int cnt  = (b < 124) ? 14 : 13;       // h-indices owned (sum = 2048)
    const int base = b * 13 + ((b < 124) ? b : 124);
    const int R = 4 * cnt;

    // ---- stage U rows into SMEM as packed bf16 pairs (natural pair order) --
    {
        const float* Us[4] = {Uf, Ui, Uc, Uo};
        for (int e = tid; e < R * 512; e += RT) {
            int r = e >> 9;
            int c4 = e & 511;
            int g = r / cnt;
            int k = r - g * cnt;
            float4 v = *(const float4*)(Us[g] + (size_t)(base + k) * HSZ + c4 * 4);
            unsigned lo = ((unsigned)__bfloat16_as_ushort(__float2bfloat16_rn(v.y)) << 16)
                        |  (unsigned)__bfloat16_as_ushort(__float2bfloat16_rn(v.x));
            unsigned hi = ((unsigned)__bfloat16_as_ushort(__float2bfloat16_rn(v.w)) << 16)
                        |  (unsigned)__bfloat16_as_ushort(__float2bfloat16_rn(v.z));
            *((uint2*)(smem + (size_t)r * 4096) + c4) = make_uint2(lo, hi);
        }
    }
    __syncthreads();

    if (cnt == 14) run_steps<14>(smem, gatev, base, warp, lane);
    else           run_steps<13>(smem, gatev, base, warp, lane);
}

// ---------------- head: fc + log_softmax over bf16 h ------------------------
__global__ __launch_bounds__(1024) void head_kernel(
    const float* __restrict__ fcw, const float* __restrict__ fcb,
    float* __restrict__ out)
{
    __shared__ float zs[OSZ];
    const int tid = threadIdx.x;
    const int warp = tid >> 5, lane = tid & 31;     // 32 warps, 2 outputs each
    const int o0 = 2 * warp, o1 = o0 + 1;
    const float* w0 = fcw + (size_t)o0 * HSZ;
    const float* w1 = fcw + (size_t)o1 * HSZ;
    float z0 = 0.f, z1 = 0.f;
#pragma unroll
    for (int i = 0; i < 8; i++) {
        int c = i * 256 + lane * 8;
        uint4 hq = *(const uint4*)(g_hb + c);       // 8 bf16 (final h, buf 0)
        float h0 = __uint_as_float(hq.x << 16), h1 = __uint_as_float(hq.x & 0xFFFF0000u);
        float h2 = __uint_as_float(hq.y << 16), h3 = __uint_as_float(hq.y & 0xFFFF0000u);
        float h4 = __uint_as_float(hq.z << 16), h5 = __uint_as_float(hq.z & 0xFFFF0000u);
        float h6 = __uint_as_float(hq.w << 16), h7 = __uint_as_float(hq.w & 0xFFFF0000u);
        float4 a0 = *(const float4*)(w0 + c);
        float4 a1 = *(const float4*)(w0 + c + 4);
        float4 b0 = *(const float4*)(w1 + c);
        float4 b1 = *(const float4*)(w1 + c + 4);
        z0 = fmaf(a0.x, h0, fmaf(a0.y, h1, fmaf(a0.z, h2, fmaf(a0.w, h3, z0))));
        z0 = fmaf(a1.x, h4, fmaf(a1.y, h5, fmaf(a1.z, h6, fmaf(a1.w, h7, z0))));
        z1 = fmaf(b0.x, h0, fmaf(b0.y, h1, fmaf(b0.z, h2, fmaf(b0.w, h3, z1))));
        z1 = fmaf(b1.x, h4, fmaf(b1.y, h5, fmaf(b1.z, h6, fmaf(b1.w, h7, z1))));
    }
#pragma unroll
    for (int o = 16; o > 0; o >>= 1) {
        z0 += __shfl_down_sync(0xffffffffu, z0, o);
        z1 += __shfl_down_sync(0xffffffffu, z1, o);
    }
    if (lane == 0) { zs[o0] = z0 + fcb[o0]; zs[o1] = z1 + fcb[o1]; }
    __syncthreads();
    if (warp == 0) {
        float a = zs[2 * lane], bq = zs[2 * lane + 1];
        float mx = fmaxf(a, bq);
#pragma unroll
        for (int o = 16; o > 0; o >>= 1) mx = fmaxf(mx, __shfl_xor_sync(0xffffffffu, mx, o));
        float s = expf(a - mx) + expf(bq - mx);
#pragma unroll
        for (int o = 16; o > 0; o >>= 1) s += __shfl_xor_sync(0xffffffffu, s, o);
        float lse = mx + logf(s);
        out[2 * lane]     = a - lse;
        out[2 * lane + 1] = bq - lse;
    }
}

// ---------------- launcher ---------------------------------------------------
extern "C" void kernel_launch(void* const* d_in, const int* in_sizes, int n_in,
                              void* d_out, int out_size)
{
    (void)in_sizes; (void)n_in; (void)out_size;
    const float* A    = (const float*)d_in[0];
    const float* Wf_w = (const float*)d_in[1];  const float* Wf_b = (const float*)d_in[2];
    const float* Uf_w = (const float*)d_in[3];  const float* Uf_b = (const float*)d_in[4];
    const float* Wi_w = (const float*)d_in[5];  const float* Wi_b = (const float*)d_in[6];
    const float* Ui_w = (const float*)d_in[7];  const float* Ui_b = (const float*)d_in[8];
    const float* Wc_w = (const float*)d_in[9];  const float* Wc_b = (const float*)d_in[10];
    const float* Uc_w = (const float*)d_in[11]; const float* Uc_b = (const float*)d_in[12];
    const float* Wo_w = (const float*)d_in[13]; const float* Wo_b = (const float*)d_in[14];
    const float* Uo_w = (const float*)d_in[15]; const float* Uo_b = (const float*)d_in[16];
    const float* fc_w = (const float*)d_in[17]; const float* fc_b = (const float*)d_in[18];
    float* out = (float*)d_out;

    cudaFuncSetAttribute(recur_kernel,
                         cudaFuncAttributeMaxDynamicSharedMemorySize, SMEM_BYTES);

    init_kernel<<<16, 256>>>();
    dim3 g(128, 32);
    xproj_kernel<<<g, 256>>>(A, Wf_w, Wi_w, Wc_w, Wo_w,
                             Wf_b, Wi_b, Wc_b, Wo_b,
                             Uf_b, Ui_b, Uc_b, Uo_b);
    recur_kernel<<<NBLK, RT, SMEM_BYTES>>>(Uf_w, Ui_w, Uc_w, Uo_w);
    head_kernel<<<1, 1024>>>(fc_w, fc_b, out);
}